// round 7
// baseline (speedup 1.0000x reference)
#include <cuda_runtime.h>
#include <cuda_bf16.h>

// loss = (1/B) * sum_b sum_{i<j} max(0, (s_i - s_j) + 0.1*(j-i)),  s = scores[argsort(labels)]
// t_k = s_sorted_k - 0.1k  ->  pair term = relu(t_i - t_j) = ((t_i-t_j)+|t_i-t_j|)/2, so
//   sum_{i<j} relu(t_i-t_j) = 0.5*[ sum_k t_k*(63-2k) + sum_m v_m*(2m-63) ],  v = sort(t) asc.
//
// Layout: 16 elements/lane, 4 lanes/row, EIGHT rows per warp (lane = oct*4 + lg).
// Bitonic-64 needs only 3 inter-lane shuffle layers (k32:d16; k64:d32,d16);
// phases k=2,4,8 are fully compile-time (pure min/max), k=16 is fully intra-lane.
// Total SHFL work is half of the 8-elems/lane layout at equal ALU work.
// Sort #1: labels as order-preserving uint32 keys with embedded 6-bit index (stable
// argsort). Score gather via smem staging. Sort #2: keys-only float sort of t.

#define BATCH 32768
#define THREADS 128
#define WARPS 4
#define ROWS_PER_WARP 8
#define GRID (BATCH / (WARPS * ROWS_PER_WARP))   // 1024 blocks

__device__ float g_partials[GRID];
__device__ unsigned int g_done = 0;

__device__ __forceinline__ float warp_sum(float v) {
#pragma unroll
    for (int o = 16; o; o >>= 1) v += __shfl_xor_sync(0xffffffffu, v, o);
    return v;
}

__device__ __forceinline__ float        tmin(float a, float b)               { return fminf(a, b); }
__device__ __forceinline__ float        tmax(float a, float b)               { return fmaxf(a, b); }
__device__ __forceinline__ unsigned int tmin(unsigned int a, unsigned int b) { return umin(a, b); }
__device__ __forceinline__ unsigned int tmax(unsigned int a, unsigned int b) { return umax(a, b); }

// compile-time direction CEs
template <class T> __device__ __forceinline__ void ceAsc (T& a, T& b) { const T lo = tmin(a, b); b = tmax(a, b); a = lo; }
template <class T> __device__ __forceinline__ void ceDesc(T& a, T& b) { const T hi = tmax(a, b); b = tmin(a, b); a = hi; }

// runtime-direction CE (R5 form — proven codegen)
template <class T>
__device__ __forceinline__ void ceSwap(T& a, T& b, bool up) {
    const bool sw = ((b < a) == up);
    const T x = a, y = b;
    a = sw ? y : x;
    b = sw ? x : y;
}

// inter-lane step at lane distance ld over 16 regs: SHFL + keep-one-side (R5 form)
template <class T>
__device__ __forceinline__ void interCE(T v[16], int ld, bool wm) {
#pragma unroll
    for (int s = 0; s < 16; ++s) {
        const T p = __shfl_xor_sync(0xffffffffu, v[s], ld);
        v[s] = ((p < v[s]) == wm) ? p : v[s];
    }
}

// intra-lane merge of a bitonic 16-seq, runtime direction: layers d=8,4,2,1
template <class T>
__device__ __forceinline__ void intra4(T v[16], bool up) {
#pragma unroll
    for (int s = 0; s < 8; ++s) ceSwap(v[s], v[s + 8], up);
#pragma unroll
    for (int g = 0; g < 16; g += 8)
#pragma unroll
        for (int s = 0; s < 4; ++s) ceSwap(v[g + s], v[g + s + 4], up);
#pragma unroll
    for (int g = 0; g < 16; g += 4) { ceSwap(v[g], v[g + 2], up); ceSwap(v[g + 1], v[g + 3], up); }
#pragma unroll
    for (int g = 0; g < 16; g += 2) ceSwap(v[g], v[g + 1], up);
}

// intra-lane merge, ascending (compile-time, pure min/max)
template <class T>
__device__ __forceinline__ void intra4Asc(T v[16]) {
#pragma unroll
    for (int s = 0; s < 8; ++s) ceAsc(v[s], v[s + 8]);
#pragma unroll
    for (int g = 0; g < 16; g += 8)
#pragma unroll
        for (int s = 0; s < 4; ++s) ceAsc(v[g + s], v[g + s + 4]);
#pragma unroll
    for (int g = 0; g < 16; g += 4) { ceAsc(v[g], v[g + 2]); ceAsc(v[g + 1], v[g + 3]); }
#pragma unroll
    for (int g = 0; g < 16; g += 2) ceAsc(v[g], v[g + 1]);
}

// ascending bitonic sort of 64 elements: idx = 16*lg + slot, lg = lane & 3
template <class T>
__device__ __forceinline__ void bitonic64(T v[16], int lg) {
    // ---- k=2: dir by (slot&2)==0, compile-time ----
#pragma unroll
    for (int g = 0; g < 16; g += 4) { ceAsc(v[g], v[g + 1]); ceDesc(v[g + 2], v[g + 3]); }
    // ---- k=4: dir by (slot&4)==0; layers d=2,1 ----
#pragma unroll
    for (int g = 0; g < 16; g += 8) {
        ceAsc (v[g + 0], v[g + 2]); ceAsc (v[g + 1], v[g + 3]);
        ceDesc(v[g + 4], v[g + 6]); ceDesc(v[g + 5], v[g + 7]);
        ceAsc (v[g + 0], v[g + 1]); ceAsc (v[g + 2], v[g + 3]);
        ceDesc(v[g + 4], v[g + 5]); ceDesc(v[g + 6], v[g + 7]);
    }
    // ---- k=8: dir by (slot&8)==0; layers d=4,2,1 ----
#pragma unroll
    for (int s = 0; s < 4; ++s) { ceAsc(v[s], v[s + 4]);  ceDesc(v[8 + s], v[12 + s]); }
#pragma unroll
    for (int g = 0; g < 8; g += 4) { ceAsc(v[g], v[g + 2]); ceAsc(v[g + 1], v[g + 3]); }
#pragma unroll
    for (int g = 8; g < 16; g += 4) { ceDesc(v[g], v[g + 2]); ceDesc(v[g + 1], v[g + 3]); }
#pragma unroll
    for (int g = 0; g < 8; g += 2) ceAsc(v[g], v[g + 1]);
#pragma unroll
    for (int g = 8; g < 16; g += 2) ceDesc(v[g], v[g + 1]);
    // ---- k=16: dir = (lg&1)==0; fully intra-lane ----
    { const bool up = (lg & 1) == 0; intra4(v, up); }
    // ---- k=32: dir = (lg&2)==0; d=16 inter (ld=1), then intra ----
    { const bool up = (lg & 2) == 0;
      interCE(v, 1, ((lg & 1) == 0) == up);
      intra4(v, up); }
    // ---- k=64: ascending; d=32 (ld=2), d=16 (ld=1), then intra asc ----
    { interCE(v, 2, (lg & 2) == 0);
      interCE(v, 1, (lg & 1) == 0);
      intra4Asc(v); }
}

// order-preserving float -> uint32 (ascending), low 6 bits carry original index
__device__ __forceinline__ unsigned int pack_key(float f, int idx) {
    unsigned int u = __float_as_uint(f);
    u ^= (unsigned int)((int)u >> 31) | 0x80000000u;
    return (u & ~63u) | (unsigned int)idx;
}

__global__ __launch_bounds__(THREADS)
void loss_kernel(const float* __restrict__ scores,
                 const float* __restrict__ labels,
                 float* __restrict__ out) {
    __shared__ float shsc[WARPS][ROWS_PER_WARP][68];  // stride 68 (%32==4): bank-rotated rows
    __shared__ float wpart[WARPS];
    __shared__ bool  isLast;

    const int warp = threadIdx.x >> 5;
    const int lane = threadIdx.x & 31;
    const int lg   = lane & 3;            // row-local lane (4 per row)
    const int oct  = lane >> 2;           // which of the 8 rows in this warp
    const int wg   = blockIdx.x * WARPS + warp;
    const int row  = wg * ROWS_PER_WARP + oct;

    // lane owns elements 16lg .. 16lg+15 of its row (4 x float4, coalesced over the warp)
    const float4* Lp = reinterpret_cast<const float4*>(labels) + row * 16 + 4 * lg;
    const float4* Sp = reinterpret_cast<const float4*>(scores) + row * 16 + 4 * lg;

    // stage scores for the post-sort gather (regs die immediately)
#pragma unroll
    for (int q = 0; q < 4; ++q) {
        const float4 S = Sp[q];
        shsc[warp][oct][16 * lg + 4 * q + 0] = S.x;
        shsc[warp][oct][16 * lg + 4 * q + 1] = S.y;
        shsc[warp][oct][16 * lg + 4 * q + 2] = S.z;
        shsc[warp][oct][16 * lg + 4 * q + 3] = S.w;
    }
    __syncwarp();

    unsigned int key[16];
#pragma unroll
    for (int q = 0; q < 4; ++q) {
        const float4 L = Lp[q];
        const int b = 16 * lg + 4 * q;
        key[4 * q + 0] = pack_key(L.x, b + 0);
        key[4 * q + 1] = pack_key(L.y, b + 1);
        key[4 * q + 2] = pack_key(L.z, b + 2);
        key[4 * q + 3] = pack_key(L.w, b + 3);
    }

    bitonic64(key, lg);                   // sort #1: by label (stable via embedded index)

    // gather scores at sorted order; t_p = s_sorted_p - 0.1p, p = 16lg + s
    const float lgf = (float)lg;
    float t[16];
#pragma unroll
    for (int s = 0; s < 16; ++s) {
        const float sv = shsc[warp][oct][(int)(key[s] & 63u)];
        t[s] = fmaf(-1.6f, lgf, sv) - 0.1f * (float)s;
    }

    // linear term: c_p = 63 - 2p = (63 - 32lg) - 2s
    const float cb = 63.0f - 32.0f * lgf;
    float acc = 0.f;
#pragma unroll
    for (int s = 0; s < 16; ++s) acc = fmaf(t[s], cb - 2.0f * (float)s, acc);

    bitonic64(t, lg);                     // sort #2: values only

    // abs term: sum_m v_m*(2m-63) = -(weighted sum at (63-2m))
    float acc2 = 0.f;
#pragma unroll
    for (int s = 0; s < 16; ++s) acc2 = fmaf(t[s], cb - 2.0f * (float)s, acc2);
    acc -= acc2;

    // ---- deterministic block reduction (32 lanes cover 8 rows) ----
    const float ws = warp_sum(acc);
    if (lane == 0) wpart[warp] = ws;
    __syncthreads();
    if (warp == 0) {
        float x = (lane < WARPS) ? wpart[lane] : 0.f;
        x = warp_sum(x);
        if (lane == 0) {
            g_partials[blockIdx.x] = x;
            __threadfence();
            isLast = (atomicAdd(&g_done, 1u) == GRID - 1);
        }
    }
    __syncthreads();

    // ---- last block: fixed-order final reduction, reset counter ----
    if (isLast) {
        float x = 0.f;
#pragma unroll
        for (int i = 0; i < GRID / THREADS; ++i)
            x += __ldcg(&g_partials[threadIdx.x + i * THREADS]);
        x = warp_sum(x);
        if (lane == 0) wpart[warp] = x;
        __syncthreads();
        if (warp == 0) {
            float y = (lane < WARPS) ? wpart[lane] : 0.f;
            y = warp_sum(y);
            if (lane == 0) {
                out[0] = y * (0.5f / (float)BATCH);
                g_done = 0;
            }
        }
    }
}

extern "C" void kernel_launch(void* const* d_in, const int* in_sizes, int n_in,
                              void* d_out, int out_size) {
    const float* scores = (const float*)d_in[0];
    const float* labels = (const float*)d_in[1];
    float* out = (float*)d_out;
    loss_kernel<<<GRID, THREADS>>>(scores, labels, out);
}